// round 3
// baseline (speedup 1.0000x reference)
#include <cuda_runtime.h>
#include <math.h>

#define B_TOT 128
#define NWIN  32
#define NTOK  343
#define HEADS 6
#define HD    32
#define CDIM  192
#define C3    576
#define MTOT  (B_TOT * NTOK)   // 43904

// Scratch (no allocations allowed)
__device__ float g_qkv[MTOT * C3];                         // 101.2 MB
__device__ float g_ao [MTOT * CDIM];                       //  33.7 MB
__device__ float g_bm [NWIN * HEADS * NTOK * NTOK];        //  90.4 MB  bias+mask fused

// ---------------------------------------------------------------------------
// tf32 helpers
// ---------------------------------------------------------------------------
__device__ __forceinline__ unsigned f2tf(float x) {
    unsigned r; asm("cvt.rna.tf32.f32 %0, %1;" : "=r"(r) : "f"(x)); return r;
}
// D += A(16x8 row) * B(8x8 col), tf32 in, fp32 accumulate
__device__ __forceinline__ void mma8(float* c, const unsigned* a, const unsigned* b) {
    asm("mma.sync.aligned.m16n8k8.row.col.f32.tf32.tf32.f32 "
        "{%0,%1,%2,%3}, {%4,%5,%6,%7}, {%8,%9}, {%0,%1,%2,%3};"
        : "+f"(c[0]), "+f"(c[1]), "+f"(c[2]), "+f"(c[3])
        : "r"(a[0]), "r"(a[1]), "r"(a[2]), "r"(a[3]), "r"(b[0]), "r"(b[1]));
}

// ---------------------------------------------------------------------------
// bm[w][h][i][j] = table[rel[i*N+j]*H + h] + mask[w][i][j]
// ---------------------------------------------------------------------------
__global__ void bm_kernel(const float* __restrict__ table,
                          const int* __restrict__ rel,
                          const float* __restrict__ mask) {
    long long idx = (long long)blockIdx.x * blockDim.x + threadIdx.x;
    const long long total = (long long)NWIN * HEADS * NTOK * NTOK;
    if (idx >= total) return;
    int ij = idx % (NTOK * NTOK);
    int wh = idx / (NTOK * NTOK);
    int h  = wh % HEADS;
    int w  = wh / HEADS;
    g_bm[idx] = table[rel[ij] * HEADS + h] + mask[(size_t)w * NTOK * NTOK + ij];
}

// ---------------------------------------------------------------------------
// Tensor-core GEMM: C[m][n] = sum_k X[m][k]*W[n][k] + bias[n]
// BM=128 BN=64 BK=16, 256 threads, warps 4(m) x 2(n), warp tile 32x32
// ---------------------------------------------------------------------------
#define BM 128
#define BN 64
#define BK 16
#define SA_STR 136   // [k][m], 136 % 32 == 8 -> frag loads conflict-free
#define SB_STR 72    // [k][n], 72 % 32 == 8

__global__ __launch_bounds__(256) void gemm_tc(const float* __restrict__ X,
                                               const float* __restrict__ W,
                                               const float* __restrict__ bias,
                                               float* __restrict__ C,
                                               int M, int N, int K) {
    __shared__ unsigned sA[BK][SA_STR];
    __shared__ unsigned sB[BK][SB_STR];
    const int m0 = blockIdx.y * BM, n0 = blockIdx.x * BN;
    const int t = threadIdx.x, lane = t & 31, warp = t >> 5;
    const int wm = warp >> 1, wn = warp & 1;
    const int grp = lane >> 2, tig = lane & 3;

    float acc[2][4][4] = {};
    const int lr  = t >> 2;          // 0..63
    const int lk4 = (t & 3) * 4;

    for (int k0 = 0; k0 < K; k0 += BK) {
        {   // A: 128x16, two float4 per thread
            float4 v0 = *(const float4*)&X[(size_t)(m0 + lr) * K + k0 + lk4];
            float4 v1 = *(const float4*)&X[(size_t)(m0 + lr + 64) * K + k0 + lk4];
            sA[lk4+0][lr] = f2tf(v0.x); sA[lk4+1][lr] = f2tf(v0.y);
            sA[lk4+2][lr] = f2tf(v0.z); sA[lk4+3][lr] = f2tf(v0.w);
            sA[lk4+0][lr+64] = f2tf(v1.x); sA[lk4+1][lr+64] = f2tf(v1.y);
            sA[lk4+2][lr+64] = f2tf(v1.z); sA[lk4+3][lr+64] = f2tf(v1.w);
        }
        {   // B: 64x16, one float4 per thread
            float4 v = *(const float4*)&W[(size_t)(n0 + lr) * K + k0 + lk4];
            sB[lk4+0][lr] = f2tf(v.x); sB[lk4+1][lr] = f2tf(v.y);
            sB[lk4+2][lr] = f2tf(v.z); sB[lk4+3][lr] = f2tf(v.w);
        }
        __syncthreads();
        #pragma unroll
        for (int ks = 0; ks < 2; ks++) {
            const int kk = ks * 8 + tig;
            unsigned af[2][4], bf[4][2];
            #pragma unroll
            for (int mt = 0; mt < 2; mt++) {
                int r = wm * 32 + mt * 16 + grp;
                af[mt][0] = sA[kk][r];     af[mt][1] = sA[kk][r + 8];
                af[mt][2] = sA[kk+4][r];   af[mt][3] = sA[kk+4][r + 8];
            }
            #pragma unroll
            for (int nt = 0; nt < 4; nt++) {
                int n = wn * 32 + nt * 8 + grp;
                bf[nt][0] = sB[kk][n];
                bf[nt][1] = sB[kk+4][n];
            }
            #pragma unroll
            for (int mt = 0; mt < 2; mt++)
                #pragma unroll
                for (int nt = 0; nt < 4; nt++)
                    mma8(acc[mt][nt], af[mt], bf[nt]);
        }
        __syncthreads();
    }
    #pragma unroll
    for (int mt = 0; mt < 2; mt++) {
        #pragma unroll
        for (int nt = 0; nt < 4; nt++) {
            int r = m0 + wm * 32 + mt * 16 + grp;
            int n = n0 + wn * 32 + nt * 8 + 2 * tig;
            float b0 = bias[n], b1 = bias[n + 1];
            *(float2*)&C[(size_t)r * N + n] =
                make_float2(acc[mt][nt][0] + b0, acc[mt][nt][1] + b1);
            *(float2*)&C[(size_t)(r + 8) * N + n] =
                make_float2(acc[mt][nt][2] + b0, acc[mt][nt][3] + b1);
        }
    }
}

// ---------------------------------------------------------------------------
// Tensor-core attention. One CTA per (b*H+h, 64-query tile). 256 threads.
// ---------------------------------------------------------------------------
#define SQ_STR 36    // [q][d], 36 % 32 == 4 -> A-frag conflict-free
#define SK_STR 36    // [j][d], B-frag (n=grp stride) -> 4 mod 32
#define SV_STR 40    // [j][d], B-frag (k=tig stride) -> 8 mod 32
#define SS_STR 412   // [q][j], 412 % 32 == 28 -> A-frag conflict-free
// floats: 64*36*2 + 64*40 + 64*412 = 33536 -> 134144 bytes
#define ATTN_SMEM_BYTES ((64*SQ_STR + 64*SK_STR + 64*SV_STR + 64*SS_STR) * 4)

__global__ __launch_bounds__(256, 1) void attn_tc(const float* __restrict__ qkv,
                                                  float* __restrict__ ao) {
    extern __shared__ float sm[];
    float* sQ = sm;                     // [64][36]
    float* sK = sQ + 64 * SQ_STR;       // [64][36]
    float* sV = sK + 64 * SK_STR;       // [64][40]
    float* sS = sV + 64 * SV_STR;       // [64][412]
    unsigned* uQ = (unsigned*)sQ;
    unsigned* uK = (unsigned*)sK;
    unsigned* uV = (unsigned*)sV;
    unsigned* uS = (unsigned*)sS;

    const int bh = blockIdx.y, b = bh / HEADS, h = bh % HEADS;
    const int q0 = blockIdx.x * 64;
    const int w = b % NWIN;
    const int t = threadIdx.x, lane = t & 31, warp = t >> 5;
    const int wm = warp & 1;            // 2-way over m
    const int wn = warp >> 1;           // 4-way over n
    const int grp = lane >> 2, tig = lane & 3;
    const float scale = 0.17677669529663687f;   // 32^-0.5

    // ---- Q tile (scaled, tf32) ----
    #pragma unroll
    for (int it = 0; it < 2; it++) {
        int idx = (it * 256 + t) * 4;
        int r = idx >> 5, d = idx & 31;
        int n = q0 + r;
        float4 v = make_float4(0.f, 0.f, 0.f, 0.f);
        if (n < NTOK) v = *(const float4*)&qkv[(size_t)(b * NTOK + n) * C3 + h * HD + d];
        uQ[r * SQ_STR + d]     = f2tf(v.x * scale);
        uQ[r * SQ_STR + d + 1] = f2tf(v.y * scale);
        uQ[r * SQ_STR + d + 2] = f2tf(v.z * scale);
        uQ[r * SQ_STR + d + 3] = f2tf(v.w * scale);
    }
    // ---- prefill sS with fused bias+mask (coalesced) ----
    const float* bm = &g_bm[(size_t)(w * HEADS + h) * NTOK * NTOK];
    for (int idx = t; idx < 64 * NTOK; idx += 256) {
        int r = idx / NTOK, j = idx - r * NTOK;
        sS[r * SS_STR + j] = (q0 + r < NTOK) ? bm[(size_t)(q0 + r) * NTOK + j] : 0.f;
    }
    __syncthreads();

    // ---- hoist Q fragments into registers (reused across all key tiles) ----
    unsigned aq[2][4][4];
    #pragma unroll
    for (int mt = 0; mt < 2; mt++)
        #pragma unroll
        for (int ks = 0; ks < 4; ks++) {
            int r = wm * 32 + mt * 16 + grp, kk = ks * 8 + tig;
            aq[mt][ks][0] = uQ[r * SQ_STR + kk];
            aq[mt][ks][1] = uQ[(r + 8) * SQ_STR + kk];
            aq[mt][ks][2] = uQ[r * SQ_STR + kk + 4];
            aq[mt][ks][3] = uQ[(r + 8) * SQ_STR + kk + 4];
        }

    // ---- S = QK^T (+prefilled bias+mask), 6 key tiles ----
    for (int kt = 0; kt < 6; kt++) {
        const int k0 = kt * 64;
        __syncthreads();
        #pragma unroll
        for (int it = 0; it < 2; it++) {
            int idx = (it * 256 + t) * 4;
            int r = idx >> 5, d = idx & 31;
            int n = k0 + r;
            float4 v = make_float4(0.f, 0.f, 0.f, 0.f);
            if (n < NTOK)
                v = *(const float4*)&qkv[(size_t)(b * NTOK + n) * C3 + CDIM + h * HD + d];
            uK[r * SK_STR + d]     = f2tf(v.x);
            uK[r * SK_STR + d + 1] = f2tf(v.y);
            uK[r * SK_STR + d + 2] = f2tf(v.z);
            uK[r * SK_STR + d + 3] = f2tf(v.w);
        }
        __syncthreads();

        float acc[2][2][4] = {};
        #pragma unroll
        for (int ks = 0; ks < 4; ks++) {
            const int kk = ks * 8 + tig;
            unsigned bf[2][2];
            #pragma unroll
            for (int nt = 0; nt < 2; nt++) {
                int n = wn * 16 + nt * 8 + grp;
                bf[nt][0] = uK[n * SK_STR + kk];
                bf[nt][1] = uK[n * SK_STR + kk + 4];
            }
            #pragma unroll
            for (int mt = 0; mt < 2; mt++)
                #pragma unroll
                for (int nt = 0; nt < 2; nt++)
                    mma8(acc[mt][nt], aq[mt][ks], bf[nt]);
        }
        #pragma unroll
        for (int mt = 0; mt < 2; mt++)
            #pragma unroll
            for (int nt = 0; nt < 2; nt++) {
                int r  = wm * 32 + mt * 16 + grp;
                int jg = k0 + wn * 16 + nt * 8 + 2 * tig;
                if (jg < NTOK) {
                    float2* p = (float2*)&sS[r * SS_STR + jg];
                    float2 v = *p;
                    v.x += acc[mt][nt][0]; v.y += acc[mt][nt][1];
                    *p = v;
                    float2* p2 = (float2*)&sS[(r + 8) * SS_STR + jg];
                    v = *p2;
                    v.x += acc[mt][nt][2]; v.y += acc[mt][nt][3];
                    *p2 = v;
                }
            }
    }
    __syncthreads();

    // ---- softmax (fp32), then convert P to tf32 in place; zero padding ----
    for (int rr = 0; rr < 8; rr++) {
        int r = warp * 8 + rr;
        float* row = &sS[r * SS_STR];
        if (q0 + r >= NTOK) {
            for (int j = lane; j < 384; j += 32) row[j] = 0.f;
            continue;
        }
        float mx = -1e30f;
        for (int j = lane; j < NTOK; j += 32) mx = fmaxf(mx, row[j]);
        #pragma unroll
        for (int o = 16; o; o >>= 1) mx = fmaxf(mx, __shfl_xor_sync(0xffffffffu, mx, o));
        float sum = 0.f;
        for (int j = lane; j < NTOK; j += 32) {
            float e = __expf(row[j] - mx);
            row[j] = e;
            sum += e;
        }
        #pragma unroll
        for (int o = 16; o; o >>= 1) sum += __shfl_xor_sync(0xffffffffu, sum, o);
        float inv = 1.f / sum;
        for (int j = lane; j < NTOK; j += 32)
            row[j] = __uint_as_float(f2tf(row[j] * inv));
        for (int j = NTOK + lane; j < 384; j += 32) row[j] = 0.f;
    }
    __syncthreads();

    // ---- O = P @ V ----
    float oacc[2][4] = {};
    for (int kt = 0; kt < 6; kt++) {
        const int k0 = kt * 64;
        #pragma unroll
        for (int it = 0; it < 2; it++) {
            int idx = (it * 256 + t) * 4;
            int r = idx >> 5, d = idx & 31;
            int n = k0 + r;
            float4 v = make_float4(0.f, 0.f, 0.f, 0.f);
            if (n < NTOK)
                v = *(const float4*)&qkv[(size_t)(b * NTOK + n) * C3 + 2 * CDIM + h * HD + d];
            uV[r * SV_STR + d]     = f2tf(v.x);
            uV[r * SV_STR + d + 1] = f2tf(v.y);
            uV[r * SV_STR + d + 2] = f2tf(v.z);
            uV[r * SV_STR + d + 3] = f2tf(v.w);
        }
        __syncthreads();
        #pragma unroll
        for (int ks = 0; ks < 8; ks++) {
            const int kk = ks * 8 + tig;
            unsigned bf[2];
            const int d = wn * 8 + grp;
            bf[0] = uV[kk * SV_STR + d];
            bf[1] = uV[(kk + 4) * SV_STR + d];
            #pragma unroll
            for (int mt = 0; mt < 2; mt++) {
                int r = wm * 32 + mt * 16 + grp;
                unsigned af[4];
                af[0] = uS[r * SS_STR + k0 + kk];
                af[1] = uS[(r + 8) * SS_STR + k0 + kk];
                af[2] = uS[r * SS_STR + k0 + kk + 4];
                af[3] = uS[(r + 8) * SS_STR + k0 + kk + 4];
                mma8(oacc[mt], af, bf);
            }
        }
        __syncthreads();
    }

    #pragma unroll
    for (int mt = 0; mt < 2; mt++) {
        int r = wm * 32 + mt * 16 + grp;
        int d = wn * 8 + 2 * tig;
        int n = q0 + r;
        if (n < NTOK)
            *(float2*)&ao[(size_t)(b * NTOK + n) * CDIM + h * HD + d] =
                make_float2(oacc[mt][0], oacc[mt][1]);
        if (n + 8 < NTOK)
            *(float2*)&ao[(size_t)(b * NTOK + n + 8) * CDIM + h * HD + d] =
                make_float2(oacc[mt][2], oacc[mt][3]);
    }
}

// ---------------------------------------------------------------------------
extern "C" void kernel_launch(void* const* d_in, const int* in_sizes, int n_in,
                              void* d_out, int out_size) {
    const float* x      = (const float*)d_in[0];
    const float* mask   = (const float*)d_in[1];
    const float* qkv_w  = (const float*)d_in[2];
    const float* qkv_b  = (const float*)d_in[3];
    const float* proj_w = (const float*)d_in[4];
    const float* proj_b = (const float*)d_in[5];
    const float* rpb    = (const float*)d_in[6];
    const int*   rel    = (const int*)d_in[7];
    float* out = (float*)d_out;

    float *p_qkv = nullptr, *p_ao = nullptr;
    cudaGetSymbolAddress((void**)&p_qkv, g_qkv);
    cudaGetSymbolAddress((void**)&p_ao,  g_ao);

    static bool attr_set = false;
    if (!attr_set) {
        cudaFuncSetAttribute(attn_tc, cudaFuncAttributeMaxDynamicSharedMemorySize,
                             ATTN_SMEM_BYTES);
        attr_set = true;
    }

    // 1) fused bias+mask precompute
    {
        long long total = (long long)NWIN * HEADS * NTOK * NTOK;
        bm_kernel<<<(int)((total + 255) / 256), 256>>>(rpb, rel, mask);
    }
    // 2) QKV GEMM
    {
        dim3 grid(C3 / BN, MTOT / BM);
        gemm_tc<<<grid, 256>>>(x, qkv_w, qkv_b, p_qkv, MTOT, C3, CDIM);
    }
    // 3) attention
    {
        dim3 grid(6, B_TOT * HEADS);
        attn_tc<<<grid, 256, ATTN_SMEM_BYTES>>>(p_qkv, p_ao);
    }
    // 4) proj GEMM
    {
        dim3 grid(CDIM / BN, MTOT / BM);
        gemm_tc<<<grid, 256>>>(p_ao, proj_w, proj_b, out, MTOT, CDIM, CDIM);
    }
}

// round 5
// speedup vs baseline: 2.0078x; 2.0078x over previous
#include <cuda_runtime.h>
#include <math.h>

#define B_TOT 128
#define NWIN  32
#define NTOK  343
#define HEADS 6
#define HD    32
#define CDIM  192
#define C3    576
#define MTOT  (B_TOT * NTOK)   // 43904

// Scratch (no allocations allowed)
__device__ float g_qkv[MTOT * C3];                     // 101.2 MB
__device__ float g_ao [MTOT * CDIM];                   //  33.7 MB
__device__ float g_bias[HEADS * NTOK * NTOK + 64];     //   2.8 MB (+pad), L2-resident

// ---------------------------------------------------------------------------
// tf32 helpers
// ---------------------------------------------------------------------------
__device__ __forceinline__ unsigned f2tf(float x) {
    unsigned r; asm("cvt.rna.tf32.f32 %0, %1;" : "=r"(r) : "f"(x)); return r;
}
__device__ __forceinline__ void mma8(float* c, const unsigned* a, const unsigned* b) {
    asm("mma.sync.aligned.m16n8k8.row.col.f32.tf32.tf32.f32 "
        "{%0,%1,%2,%3}, {%4,%5,%6,%7}, {%8,%9}, {%0,%1,%2,%3};"
        : "+f"(c[0]), "+f"(c[1]), "+f"(c[2]), "+f"(c[3])
        : "r"(a[0]), "r"(a[1]), "r"(a[2]), "r"(a[3]), "r"(b[0]), "r"(b[1]));
}

// ---------------------------------------------------------------------------
// bias gather: g_bias[h][i][j] = table[rel[i*N+j]*H + h]
// ---------------------------------------------------------------------------
__global__ void bias_kernel(const float* __restrict__ table,
                            const int* __restrict__ rel) {
    int idx = blockIdx.x * blockDim.x + threadIdx.x;
    const int total = HEADS * NTOK * NTOK;
    if (idx >= total) return;
    int h  = idx / (NTOK * NTOK);
    int ij = idx % (NTOK * NTOK);
    g_bias[idx] = table[rel[ij] * HEADS + h];
}

// ---------------------------------------------------------------------------
// Tensor-core GEMM: C[m][n] = sum_k X[m][k]*W[n][k] + bias[n]
// ---------------------------------------------------------------------------
#define BM 128
#define BN 64
#define BK 16
#define SA_STR 136
#define SB_STR 72

__global__ __launch_bounds__(256) void gemm_tc(const float* __restrict__ X,
                                               const float* __restrict__ W,
                                               const float* __restrict__ bias,
                                               float* __restrict__ C,
                                               int M, int N, int K) {
    __shared__ unsigned sA[BK][SA_STR];
    __shared__ unsigned sB[BK][SB_STR];
    const int m0 = blockIdx.y * BM, n0 = blockIdx.x * BN;
    const int t = threadIdx.x, lane = t & 31, warp = t >> 5;
    const int wm = warp >> 1, wn = warp & 1;
    const int grp = lane >> 2, tig = lane & 3;

    float acc[2][4][4] = {};
    const int lr  = t >> 2;
    const int lk4 = (t & 3) * 4;

    for (int k0 = 0; k0 < K; k0 += BK) {
        {
            float4 v0 = *(const float4*)&X[(size_t)(m0 + lr) * K + k0 + lk4];
            float4 v1 = *(const float4*)&X[(size_t)(m0 + lr + 64) * K + k0 + lk4];
            sA[lk4+0][lr] = f2tf(v0.x); sA[lk4+1][lr] = f2tf(v0.y);
            sA[lk4+2][lr] = f2tf(v0.z); sA[lk4+3][lr] = f2tf(v0.w);
            sA[lk4+0][lr+64] = f2tf(v1.x); sA[lk4+1][lr+64] = f2tf(v1.y);
            sA[lk4+2][lr+64] = f2tf(v1.z); sA[lk4+3][lr+64] = f2tf(v1.w);
        }
        {
            float4 v = *(const float4*)&W[(size_t)(n0 + lr) * K + k0 + lk4];
            sB[lk4+0][lr] = f2tf(v.x); sB[lk4+1][lr] = f2tf(v.y);
            sB[lk4+2][lr] = f2tf(v.z); sB[lk4+3][lr] = f2tf(v.w);
        }
        __syncthreads();
        #pragma unroll
        for (int ks = 0; ks < 2; ks++) {
            const int kk = ks * 8 + tig;
            unsigned af[2][4], bf[4][2];
            #pragma unroll
            for (int mt = 0; mt < 2; mt++) {
                int r = wm * 32 + mt * 16 + grp;
                af[mt][0] = sA[kk][r];     af[mt][1] = sA[kk][r + 8];
                af[mt][2] = sA[kk+4][r];   af[mt][3] = sA[kk+4][r + 8];
            }
            #pragma unroll
            for (int nt = 0; nt < 4; nt++) {
                int n = wn * 32 + nt * 8 + grp;
                bf[nt][0] = sB[kk][n];
                bf[nt][1] = sB[kk+4][n];
            }
            #pragma unroll
            for (int mt = 0; mt < 2; mt++)
                #pragma unroll
                for (int nt = 0; nt < 4; nt++)
                    mma8(acc[mt][nt], af[mt], bf[nt]);
        }
        __syncthreads();
    }
    #pragma unroll
    for (int mt = 0; mt < 2; mt++) {
        #pragma unroll
        for (int nt = 0; nt < 4; nt++) {
            int r = m0 + wm * 32 + mt * 16 + grp;
            int n = n0 + wn * 32 + nt * 8 + 2 * tig;
            float b0 = bias[n], b1 = bias[n + 1];
            *(float2*)&C[(size_t)r * N + n] =
                make_float2(acc[mt][nt][0] + b0, acc[mt][nt][1] + b1);
            *(float2*)&C[(size_t)(r + 8) * N + n] =
                make_float2(acc[mt][nt][2] + b0, acc[mt][nt][3] + b1);
        }
    }
}

// ---------------------------------------------------------------------------
// Flash attention: 128 queries/CTA, stream K/V in 64-key tiles, S in registers
// ---------------------------------------------------------------------------
#define QT    128
#define SKSTR 36
#define SVSTR 40
#define PSTR  68
// floats: 128*68 + 64*36 + 64*40 = 13568 -> 54272 bytes
#define FLASH_SMEM_BYTES ((128*PSTR + 64*SKSTR + 64*SVSTR) * 4)
#define L2E 1.4426950408889634f

__global__ __launch_bounds__(256, 2) void attn_flash(const float* __restrict__ qkv,
                                                     const float* __restrict__ mask,
                                                     float* __restrict__ ao) {
    extern __shared__ float sm[];
    float* sP = sm;                  // [128][68]: bias+mask tile, then P; Q staging at start
    float* sK = sP + 128 * PSTR;     // [64][36]
    float* sV = sK + 64 * SKSTR;     // [64][40]
    unsigned* uP = (unsigned*)sP;
    unsigned* uK = (unsigned*)sK;
    unsigned* uV = (unsigned*)sV;

    const int bh = blockIdx.y, b = bh / HEADS, h = bh % HEADS;
    const int q0 = blockIdx.x * QT;
    const int w = b % NWIN;
    const int t = threadIdx.x, lane = t & 31, warp = t >> 5;
    const int grp = lane >> 2, tig = lane & 3;
    const float qs = 0.17677669529663687f * L2E;   // hd^-0.5 * log2(e)

    // ---- stage Q (scaled, tf32) into sP region, stride 36 ----
    #pragma unroll
    for (int it = 0; it < 4; it++) {
        int f = it * 256 + t;               // 1024 float4s
        int r = f >> 3, d = (f & 7) * 4;
        int n = q0 + r;
        float4 v = make_float4(0.f, 0.f, 0.f, 0.f);
        if (n < NTOK) v = *(const float4*)&qkv[(size_t)(b * NTOK + n) * C3 + h * HD + d];
        uP[r * 36 + d]     = f2tf(v.x * qs);
        uP[r * 36 + d + 1] = f2tf(v.y * qs);
        uP[r * 36 + d + 2] = f2tf(v.z * qs);
        uP[r * 36 + d + 3] = f2tf(v.w * qs);
    }
    __syncthreads();

    // ---- Q fragments (warp owns rows warp*16 .. +15) ----
    unsigned aq[4][4];
    const int qr = warp * 16 + grp;
    #pragma unroll
    for (int ks = 0; ks < 4; ks++) {
        int kk = ks * 8 + tig;
        aq[ks][0] = uP[qr * 36 + kk];
        aq[ks][1] = uP[(qr + 8) * 36 + kk];
        aq[ks][2] = uP[qr * 36 + kk + 4];
        aq[ks][3] = uP[(qr + 8) * 36 + kk + 4];
    }
    __syncthreads();   // sP free for bias+mask staging

    float oacc[4][4] = {};
    float mrow[2] = {-1e30f, -1e30f};
    float lrow[2] = {0.f, 0.f};

    const float* bias_h = g_bias + (size_t)h * NTOK * NTOK;
    const float* mask_w = mask + (size_t)w * NTOK * NTOK;

    for (int kt = 0; kt < 6; kt++) {
        const int k0 = kt * 64;
        // ---- stage K,V tiles ----
        #pragma unroll
        for (int it = 0; it < 2; it++) {
            int f = it * 256 + t;           // 512 float4s
            int r = f >> 3, d = (f & 7) * 4;
            int n = k0 + r;
            float4 kv = make_float4(0.f, 0.f, 0.f, 0.f);
            float4 vv = make_float4(0.f, 0.f, 0.f, 0.f);
            if (n < NTOK) {
                kv = *(const float4*)&qkv[(size_t)(b * NTOK + n) * C3 + CDIM + h * HD + d];
                vv = *(const float4*)&qkv[(size_t)(b * NTOK + n) * C3 + 2 * CDIM + h * HD + d];
            }
            uK[r * SKSTR + d]     = f2tf(kv.x);
            uK[r * SKSTR + d + 1] = f2tf(kv.y);
            uK[r * SKSTR + d + 2] = f2tf(kv.z);
            uK[r * SKSTR + d + 3] = f2tf(kv.w);
            uV[r * SVSTR + d]     = f2tf(vv.x);
            uV[r * SVSTR + d + 1] = f2tf(vv.y);
            uV[r * SVSTR + d + 2] = f2tf(vv.z);
            uV[r * SVSTR + d + 3] = f2tf(vv.w);
        }
        // ---- stage (bias+mask)*log2e tile into sP[128][64] ----
        // SCALAR loads: bias/mask rows have stride NTOK=343 (odd) -> NOT 16B
        // aligned; float4 here faulted in R4. Flat index keeps it coalesced.
        #pragma unroll
        for (int it = 0; it < 32; it++) {
            int e = it * 256 + t;           // 8192 elements
            int r = e >> 6, c = e & 63;
            int i  = q0 + r;
            int j  = k0 + c;
            float v;
            if (i < NTOK && j < NTOK) {
                size_t off = (size_t)i * NTOK + j;
                v = (bias_h[off] + mask_w[off]) * L2E;
            } else {
                v = -1e30f;
            }
            sP[r * PSTR + c] = v;
        }
        __syncthreads();

        // ---- S = Q @ K^T (registers) ----
        float sc[8][4] = {};
        #pragma unroll
        for (int ks = 0; ks < 4; ks++) {
            int kk = ks * 8 + tig;
            #pragma unroll
            for (int nt = 0; nt < 8; nt++) {
                int n = nt * 8 + grp;
                unsigned bf[2] = { uK[n * SKSTR + kk], uK[n * SKSTR + kk + 4] };
                mma8(sc[nt], aq[ks], bf);
            }
        }
        // ---- add staged bias+mask ----
        #pragma unroll
        for (int nt = 0; nt < 8; nt++) {
            float2 b0 = *(float2*)&sP[qr * PSTR + nt * 8 + 2 * tig];
            float2 b1 = *(float2*)&sP[(qr + 8) * PSTR + nt * 8 + 2 * tig];
            sc[nt][0] += b0.x; sc[nt][1] += b0.y;
            sc[nt][2] += b1.x; sc[nt][3] += b1.y;
        }
        // ---- online softmax update (per row-half) ----
        #pragma unroll
        for (int rh = 0; rh < 2; rh++) {
            float tmax = -1e30f;
            #pragma unroll
            for (int nt = 0; nt < 8; nt++)
                tmax = fmaxf(tmax, fmaxf(sc[nt][2 * rh], sc[nt][2 * rh + 1]));
            tmax = fmaxf(tmax, __shfl_xor_sync(0xffffffffu, tmax, 1));
            tmax = fmaxf(tmax, __shfl_xor_sync(0xffffffffu, tmax, 2));
            float mnew  = fmaxf(mrow[rh], tmax);
            float alpha = exp2f(mrow[rh] - mnew);
            mrow[rh] = mnew;
            float tsum = 0.f;
            #pragma unroll
            for (int nt = 0; nt < 8; nt++) {
                float p0 = exp2f(sc[nt][2 * rh]     - mnew);
                float p1 = exp2f(sc[nt][2 * rh + 1] - mnew);
                sc[nt][2 * rh] = p0; sc[nt][2 * rh + 1] = p1;
                tsum += p0 + p1;
            }
            tsum += __shfl_xor_sync(0xffffffffu, tsum, 1);
            tsum += __shfl_xor_sync(0xffffffffu, tsum, 2);
            lrow[rh] = lrow[rh] * alpha + tsum;
            #pragma unroll
            for (int nt = 0; nt < 4; nt++) {
                oacc[nt][2 * rh]     *= alpha;
                oacc[nt][2 * rh + 1] *= alpha;
            }
        }
        // ---- write P (tf32) to warp-private sP patch, re-fragment ----
        #pragma unroll
        for (int nt = 0; nt < 8; nt++) {
            *(float2*)&sP[qr * PSTR + nt * 8 + 2 * tig] = make_float2(
                __uint_as_float(f2tf(sc[nt][0])), __uint_as_float(f2tf(sc[nt][1])));
            *(float2*)&sP[(qr + 8) * PSTR + nt * 8 + 2 * tig] = make_float2(
                __uint_as_float(f2tf(sc[nt][2])), __uint_as_float(f2tf(sc[nt][3])));
        }
        __syncwarp();
        // ---- O += P @ V ----
        #pragma unroll
        for (int ks = 0; ks < 8; ks++) {
            int kk = ks * 8 + tig;
            unsigned af[4];
            af[0] = uP[qr * PSTR + kk];
            af[1] = uP[(qr + 8) * PSTR + kk];
            af[2] = uP[qr * PSTR + kk + 4];
            af[3] = uP[(qr + 8) * PSTR + kk + 4];
            #pragma unroll
            for (int nt = 0; nt < 4; nt++) {
                int d = nt * 8 + grp;
                unsigned bf[2] = { uV[kk * SVSTR + d], uV[(kk + 4) * SVSTR + d] };
                mma8(oacc[nt], af, bf);
            }
        }
        __syncthreads();
    }

    // ---- normalize + store ----
    float inv0 = 1.f / lrow[0];
    float inv1 = 1.f / lrow[1];
    int r0 = q0 + qr;
    #pragma unroll
    for (int nt = 0; nt < 4; nt++) {
        int d = h * HD + nt * 8 + 2 * tig;
        if (r0 < NTOK)
            *(float2*)&ao[(size_t)(b * NTOK + r0) * CDIM + d] =
                make_float2(oacc[nt][0] * inv0, oacc[nt][1] * inv0);
        if (r0 + 8 < NTOK)
            *(float2*)&ao[(size_t)(b * NTOK + r0 + 8) * CDIM + d] =
                make_float2(oacc[nt][2] * inv1, oacc[nt][3] * inv1);
    }
}

// ---------------------------------------------------------------------------
extern "C" void kernel_launch(void* const* d_in, const int* in_sizes, int n_in,
                              void* d_out, int out_size) {
    const float* x      = (const float*)d_in[0];
    const float* mask   = (const float*)d_in[1];
    const float* qkv_w  = (const float*)d_in[2];
    const float* qkv_b  = (const float*)d_in[3];
    const float* proj_w = (const float*)d_in[4];
    const float* proj_b = (const float*)d_in[5];
    const float* rpb    = (const float*)d_in[6];
    const int*   rel    = (const int*)d_in[7];
    float* out = (float*)d_out;

    float *p_qkv = nullptr, *p_ao = nullptr;
    cudaGetSymbolAddress((void**)&p_qkv, g_qkv);
    cudaGetSymbolAddress((void**)&p_ao,  g_ao);

    static bool attr_set = false;
    if (!attr_set) {
        cudaFuncSetAttribute(attn_flash, cudaFuncAttributeMaxDynamicSharedMemorySize,
                             FLASH_SMEM_BYTES);
        attr_set = true;
    }

    // 1) bias gather (small, L2-resident table)
    {
        int total = HEADS * NTOK * NTOK;
        bias_kernel<<<(total + 255) / 256, 256>>>(rpb, rel);
    }
    // 2) QKV GEMM
    {
        dim3 grid(C3 / BN, MTOT / BM);
        gemm_tc<<<grid, 256>>>(x, qkv_w, qkv_b, p_qkv, MTOT, C3, CDIM);
    }
    // 3) flash attention
    {
        dim3 grid(3, B_TOT * HEADS);
        attn_flash<<<grid, 256, FLASH_SMEM_BYTES>>>(p_qkv, mask, p_ao);
    }
    // 4) proj GEMM
    {
        dim3 grid(CDIM / BN, MTOT / BM);
        gemm_tc<<<grid, 256>>>(p_ao, proj_w, proj_b, out, MTOT, CDIM, CDIM);
    }
}

// round 6
// speedup vs baseline: 2.8033x; 1.3962x over previous
#include <cuda_runtime.h>
#include <math.h>

#define B_TOT 128
#define NWIN  32
#define NTOK  343
#define HEADS 6
#define HD    32
#define CDIM  192
#define C3    576
#define MTOT  (B_TOT * NTOK)   // 43904
#define JPAD  384
#define L2E   1.4426950408889634f

// Scratch (no allocations allowed)
__device__ float g_qkv[MTOT * C3];                     // 101.2 MB
__device__ float g_ao [MTOT * CDIM];                   //  33.7 MB
__device__ float g_biasp[HEADS * NTOK * JPAD];         //   3.2 MB (L2-resident, *L2E, padded)
__device__ float g_maskp[NWIN  * NTOK * JPAD];         //  16.9 MB (L2-resident, *L2E, padded)

// ---------------------------------------------------------------------------
// tf32 helpers
// ---------------------------------------------------------------------------
__device__ __forceinline__ unsigned f2tf(float x) {
    unsigned r; asm("cvt.rna.tf32.f32 %0, %1;" : "=r"(r) : "f"(x)); return r;
}
__device__ __forceinline__ void mma8(float* c, const unsigned* a, const unsigned* b) {
    asm("mma.sync.aligned.m16n8k8.row.col.f32.tf32.tf32.f32 "
        "{%0,%1,%2,%3}, {%4,%5,%6,%7}, {%8,%9}, {%0,%1,%2,%3};"
        : "+f"(c[0]), "+f"(c[1]), "+f"(c[2]), "+f"(c[3])
        : "r"(a[0]), "r"(a[1]), "r"(a[2]), "r"(a[3]), "r"(b[0]), "r"(b[1]));
}

// ---------------------------------------------------------------------------
// Precompute padded, log2e-scaled bias and mask tables
// ---------------------------------------------------------------------------
__global__ void padb_kernel(const float* __restrict__ table,
                            const int* __restrict__ rel) {
    int idx = blockIdx.x * blockDim.x + threadIdx.x;
    if (idx >= HEADS * NTOK * JPAD) return;
    int j  = idx % JPAD;
    int hi = idx / JPAD;
    int i  = hi % NTOK, h = hi / NTOK;
    g_biasp[idx] = (j < NTOK) ? table[rel[i * NTOK + j] * HEADS + h] * L2E : -1e30f;
}
__global__ void padm_kernel(const float* __restrict__ mask) {
    int idx = blockIdx.x * blockDim.x + threadIdx.x;
    if (idx >= NWIN * NTOK * JPAD) return;
    int j  = idx % JPAD;
    int wi = idx / JPAD;
    int i  = wi % NTOK, w = wi / NTOK;
    g_maskp[idx] = (j < NTOK) ? mask[((size_t)w * NTOK + i) * NTOK + j] * L2E : -1e30f;
}

// ---------------------------------------------------------------------------
// Pipelined tensor-core GEMM: C[m][n] = sum_k X[m][k]*W[n][k] + bias[n]
// K compile-time; double-buffered smem; gmem prefetch overlapped with compute
// ---------------------------------------------------------------------------
#define BM 128
#define BN 64
#define BK 16
#define SA_STR 136
#define SB_STR 72

template<int K>
__global__ __launch_bounds__(256) void gemm_tc(const float* __restrict__ X,
                                               const float* __restrict__ W,
                                               const float* __restrict__ bias,
                                               float* __restrict__ C,
                                               int M, int N) {
    __shared__ unsigned sA[2][BK][SA_STR];
    __shared__ unsigned sB[2][BK][SB_STR];
    const int m0 = blockIdx.y * BM, n0 = blockIdx.x * BN;
    const int t = threadIdx.x, lane = t & 31, warp = t >> 5;
    const int wm = warp >> 1, wn = warp & 1;
    const int grp = lane >> 2, tig = lane & 3;
    const int lr  = t >> 2;
    const int lk4 = (t & 3) * 4;

    const float* pA0 = &X[(size_t)(m0 + lr) * K + lk4];
    const float* pA1 = &X[(size_t)(m0 + lr + 64) * K + lk4];
    const float* pB  = &W[(size_t)(n0 + lr) * K + lk4];

    float4 ra0 = *(const float4*)pA0;
    float4 ra1 = *(const float4*)pA1;
    float4 rb  = *(const float4*)pB;
    {
        sA[0][lk4+0][lr] = f2tf(ra0.x); sA[0][lk4+1][lr] = f2tf(ra0.y);
        sA[0][lk4+2][lr] = f2tf(ra0.z); sA[0][lk4+3][lr] = f2tf(ra0.w);
        sA[0][lk4+0][lr+64] = f2tf(ra1.x); sA[0][lk4+1][lr+64] = f2tf(ra1.y);
        sA[0][lk4+2][lr+64] = f2tf(ra1.z); sA[0][lk4+3][lr+64] = f2tf(ra1.w);
        sB[0][lk4+0][lr] = f2tf(rb.x); sB[0][lk4+1][lr] = f2tf(rb.y);
        sB[0][lk4+2][lr] = f2tf(rb.z); sB[0][lk4+3][lr] = f2tf(rb.w);
    }
    __syncthreads();

    float acc[2][4][4] = {};
    constexpr int NCH = K / BK;

    #pragma unroll
    for (int ch = 0; ch < NCH; ch++) {
        const int p = ch & 1;
        if (ch + 1 < NCH) {   // prefetch next chunk (overlaps with compute)
            ra0 = *(const float4*)(pA0 + (ch + 1) * BK);
            ra1 = *(const float4*)(pA1 + (ch + 1) * BK);
            rb  = *(const float4*)(pB  + (ch + 1) * BK);
        }
        #pragma unroll
        for (int ks = 0; ks < 2; ks++) {
            const int kk = ks * 8 + tig;
            unsigned af[2][4], bf[4][2];
            #pragma unroll
            for (int mt = 0; mt < 2; mt++) {
                int r = wm * 32 + mt * 16 + grp;
                af[mt][0] = sA[p][kk][r];     af[mt][1] = sA[p][kk][r + 8];
                af[mt][2] = sA[p][kk+4][r];   af[mt][3] = sA[p][kk+4][r + 8];
            }
            #pragma unroll
            for (int nt = 0; nt < 4; nt++) {
                int n = wn * 32 + nt * 8 + grp;
                bf[nt][0] = sB[p][kk][n];
                bf[nt][1] = sB[p][kk+4][n];
            }
            #pragma unroll
            for (int mt = 0; mt < 2; mt++)
                #pragma unroll
                for (int nt = 0; nt < 4; nt++)
                    mma8(acc[mt][nt], af[mt], bf[nt]);
        }
        if (ch + 1 < NCH) {
            const int q = 1 - p;
            sA[q][lk4+0][lr] = f2tf(ra0.x); sA[q][lk4+1][lr] = f2tf(ra0.y);
            sA[q][lk4+2][lr] = f2tf(ra0.z); sA[q][lk4+3][lr] = f2tf(ra0.w);
            sA[q][lk4+0][lr+64] = f2tf(ra1.x); sA[q][lk4+1][lr+64] = f2tf(ra1.y);
            sA[q][lk4+2][lr+64] = f2tf(ra1.z); sA[q][lk4+3][lr+64] = f2tf(ra1.w);
            sB[q][lk4+0][lr] = f2tf(rb.x); sB[q][lk4+1][lr] = f2tf(rb.y);
            sB[q][lk4+2][lr] = f2tf(rb.z); sB[q][lk4+3][lr] = f2tf(rb.w);
            __syncthreads();
        }
    }
    #pragma unroll
    for (int mt = 0; mt < 2; mt++) {
        #pragma unroll
        for (int nt = 0; nt < 4; nt++) {
            int r = m0 + wm * 32 + mt * 16 + grp;
            int n = n0 + wn * 32 + nt * 8 + 2 * tig;
            float b0 = bias[n], b1 = bias[n + 1];
            *(float2*)&C[(size_t)r * N + n] =
                make_float2(acc[mt][nt][0] + b0, acc[mt][nt][1] + b1);
            *(float2*)&C[(size_t)(r + 8) * N + n] =
                make_float2(acc[mt][nt][2] + b0, acc[mt][nt][3] + b1);
        }
    }
}

// ---------------------------------------------------------------------------
// Flash attention: 128 queries/CTA, stream K/V in 64-key tiles, S in registers
// ---------------------------------------------------------------------------
#define QT    128
#define SKSTR 36
#define SVSTR 40
#define PSTR  68
#define FLASH_SMEM_BYTES ((128*PSTR + 64*SKSTR + 64*SVSTR) * 4)

__global__ __launch_bounds__(256, 2) void attn_flash(const float* __restrict__ qkv,
                                                     float* __restrict__ ao) {
    extern __shared__ float sm[];
    float* sP = sm;                  // [128][68]: Q staging, then bias+mask / P
    float* sK = sP + 128 * PSTR;     // [64][36]
    float* sV = sK + 64 * SKSTR;     // [64][40]
    unsigned* uP = (unsigned*)sP;
    unsigned* uK = (unsigned*)sK;
    unsigned* uV = (unsigned*)sV;

    const int bh = blockIdx.y, b = bh / HEADS, h = bh % HEADS;
    const int q0 = blockIdx.x * QT;
    const int w = b % NWIN;
    const int t = threadIdx.x, lane = t & 31, warp = t >> 5;
    const int grp = lane >> 2, tig = lane & 3;
    const float qs = 0.17677669529663687f * L2E;   // hd^-0.5 * log2(e)

    // ---- stage Q (scaled, tf32) into sP region, stride 36 ----
    #pragma unroll
    for (int it = 0; it < 4; it++) {
        int f = it * 256 + t;
        int r = f >> 3, d = (f & 7) * 4;
        int n = q0 + r;
        float4 v = make_float4(0.f, 0.f, 0.f, 0.f);
        if (n < NTOK) v = *(const float4*)&qkv[(size_t)(b * NTOK + n) * C3 + h * HD + d];
        uP[r * 36 + d]     = f2tf(v.x * qs);
        uP[r * 36 + d + 1] = f2tf(v.y * qs);
        uP[r * 36 + d + 2] = f2tf(v.z * qs);
        uP[r * 36 + d + 3] = f2tf(v.w * qs);
    }
    __syncthreads();

    // ---- Q fragments (warp owns rows warp*16 .. +15) ----
    unsigned aq[4][4];
    const int qr = warp * 16 + grp;
    #pragma unroll
    for (int ks = 0; ks < 4; ks++) {
        int kk = ks * 8 + tig;
        aq[ks][0] = uP[qr * 36 + kk];
        aq[ks][1] = uP[(qr + 8) * 36 + kk];
        aq[ks][2] = uP[qr * 36 + kk + 4];
        aq[ks][3] = uP[(qr + 8) * 36 + kk + 4];
    }
    __syncthreads();   // sP free for bias+mask staging

    float oacc[4][4] = {};
    float mrow[2] = {-1e30f, -1e30f};
    float lrow[2] = {0.f, 0.f};

    const float* biasp = g_biasp + (size_t)h * NTOK * JPAD;
    const float* maskp = g_maskp + (size_t)w * NTOK * JPAD;

    for (int kt = 0; kt < 6; kt++) {
        const int k0 = kt * 64;
        // ---- stage K,V tiles ----
        #pragma unroll
        for (int it = 0; it < 2; it++) {
            int f = it * 256 + t;
            int r = f >> 3, d = (f & 7) * 4;
            int n = k0 + r;
            float4 kv = make_float4(0.f, 0.f, 0.f, 0.f);
            float4 vv = make_float4(0.f, 0.f, 0.f, 0.f);
            if (n < NTOK) {
                kv = *(const float4*)&qkv[(size_t)(b * NTOK + n) * C3 + CDIM + h * HD + d];
                vv = *(const float4*)&qkv[(size_t)(b * NTOK + n) * C3 + 2 * CDIM + h * HD + d];
            }
            uK[r * SKSTR + d]     = f2tf(kv.x);
            uK[r * SKSTR + d + 1] = f2tf(kv.y);
            uK[r * SKSTR + d + 2] = f2tf(kv.z);
            uK[r * SKSTR + d + 3] = f2tf(kv.w);
            uV[r * SVSTR + d]     = f2tf(vv.x);
            uV[r * SVSTR + d + 1] = f2tf(vv.y);
            uV[r * SVSTR + d + 2] = f2tf(vv.z);
            uV[r * SVSTR + d + 3] = f2tf(vv.w);
        }
        // ---- stage (bias+mask) tile (padded, pre-scaled, float4) ----
        #pragma unroll
        for (int it = 0; it < 8; it++) {
            int f = it * 256 + t;               // 2048 float4s
            int r = f >> 4, c4 = (f & 15) * 4;
            int i = q0 + r; if (i > NTOK - 1) i = NTOK - 1;
            float4 bv = *(const float4*)&biasp[i * JPAD + k0 + c4];
            float4 mv = *(const float4*)&maskp[i * JPAD + k0 + c4];
            *(float4*)&sP[r * PSTR + c4] = make_float4(bv.x + mv.x, bv.y + mv.y,
                                                       bv.z + mv.z, bv.w + mv.w);
        }
        __syncthreads();

        // ---- S = Q @ K^T (registers) ----
        float sc[8][4] = {};
        #pragma unroll
        for (int ks = 0; ks < 4; ks++) {
            int kk = ks * 8 + tig;
            #pragma unroll
            for (int nt = 0; nt < 8; nt++) {
                int n = nt * 8 + grp;
                unsigned bf[2] = { uK[n * SKSTR + kk], uK[n * SKSTR + kk + 4] };
                mma8(sc[nt], aq[ks], bf);
            }
        }
        // ---- add staged bias+mask ----
        #pragma unroll
        for (int nt = 0; nt < 8; nt++) {
            float2 b0 = *(float2*)&sP[qr * PSTR + nt * 8 + 2 * tig];
            float2 b1 = *(float2*)&sP[(qr + 8) * PSTR + nt * 8 + 2 * tig];
            sc[nt][0] += b0.x; sc[nt][1] += b0.y;
            sc[nt][2] += b1.x; sc[nt][3] += b1.y;
        }
        // ---- online softmax update (per row-half) ----
        #pragma unroll
        for (int rh = 0; rh < 2; rh++) {
            float tmax = -1e30f;
            #pragma unroll
            for (int nt = 0; nt < 8; nt++)
                tmax = fmaxf(tmax, fmaxf(sc[nt][2 * rh], sc[nt][2 * rh + 1]));
            tmax = fmaxf(tmax, __shfl_xor_sync(0xffffffffu, tmax, 1));
            tmax = fmaxf(tmax, __shfl_xor_sync(0xffffffffu, tmax, 2));
            float mnew  = fmaxf(mrow[rh], tmax);
            float alpha = exp2f(mrow[rh] - mnew);
            mrow[rh] = mnew;
            float tsum = 0.f;
            #pragma unroll
            for (int nt = 0; nt < 8; nt++) {
                float p0 = exp2f(sc[nt][2 * rh]     - mnew);
                float p1 = exp2f(sc[nt][2 * rh + 1] - mnew);
                sc[nt][2 * rh] = p0; sc[nt][2 * rh + 1] = p1;
                tsum += p0 + p1;
            }
            tsum += __shfl_xor_sync(0xffffffffu, tsum, 1);
            tsum += __shfl_xor_sync(0xffffffffu, tsum, 2);
            lrow[rh] = lrow[rh] * alpha + tsum;
            #pragma unroll
            for (int nt = 0; nt < 4; nt++) {
                oacc[nt][2 * rh]     *= alpha;
                oacc[nt][2 * rh + 1] *= alpha;
            }
        }
        // ---- write P (tf32) to warp-private sP patch, re-fragment ----
        #pragma unroll
        for (int nt = 0; nt < 8; nt++) {
            *(float2*)&sP[qr * PSTR + nt * 8 + 2 * tig] = make_float2(
                __uint_as_float(f2tf(sc[nt][0])), __uint_as_float(f2tf(sc[nt][1])));
            *(float2*)&sP[(qr + 8) * PSTR + nt * 8 + 2 * tig] = make_float2(
                __uint_as_float(f2tf(sc[nt][2])), __uint_as_float(f2tf(sc[nt][3])));
        }
        __syncwarp();
        // ---- O += P @ V ----
        #pragma unroll
        for (int ks = 0; ks < 8; ks++) {
            int kk = ks * 8 + tig;
            unsigned af[4];
            af[0] = uP[qr * PSTR + kk];
            af[1] = uP[(qr + 8) * PSTR + kk];
            af[2] = uP[qr * PSTR + kk + 4];
            af[3] = uP[(qr + 8) * PSTR + kk + 4];
            #pragma unroll
            for (int nt = 0; nt < 4; nt++) {
                int d = nt * 8 + grp;
                unsigned bf[2] = { uV[kk * SVSTR + d], uV[(kk + 4) * SVSTR + d] };
                mma8(oacc[nt], af, bf);
            }
        }
        __syncthreads();
    }

    // ---- normalize + store ----
    float inv0 = 1.f / lrow[0];
    float inv1 = 1.f / lrow[1];
    int r0 = q0 + qr;
    #pragma unroll
    for (int nt = 0; nt < 4; nt++) {
        int d = h * HD + nt * 8 + 2 * tig;
        if (r0 < NTOK)
            *(float2*)&ao[(size_t)(b * NTOK + r0) * CDIM + d] =
                make_float2(oacc[nt][0] * inv0, oacc[nt][1] * inv0);
        if (r0 + 8 < NTOK)
            *(float2*)&ao[(size_t)(b * NTOK + r0 + 8) * CDIM + d] =
                make_float2(oacc[nt][2] * inv1, oacc[nt][3] * inv1);
    }
}

// ---------------------------------------------------------------------------
extern "C" void kernel_launch(void* const* d_in, const int* in_sizes, int n_in,
                              void* d_out, int out_size) {
    const float* x      = (const float*)d_in[0];
    const float* mask   = (const float*)d_in[1];
    const float* qkv_w  = (const float*)d_in[2];
    const float* qkv_b  = (const float*)d_in[3];
    const float* proj_w = (const float*)d_in[4];
    const float* proj_b = (const float*)d_in[5];
    const float* rpb    = (const float*)d_in[6];
    const int*   rel    = (const int*)d_in[7];
    float* out = (float*)d_out;

    float *p_qkv = nullptr, *p_ao = nullptr;
    cudaGetSymbolAddress((void**)&p_qkv, g_qkv);
    cudaGetSymbolAddress((void**)&p_ao,  g_ao);

    static bool attr_set = false;
    if (!attr_set) {
        cudaFuncSetAttribute(attn_flash, cudaFuncAttributeMaxDynamicSharedMemorySize,
                             FLASH_SMEM_BYTES);
        attr_set = true;
    }

    // 1) padded bias / mask precompute
    {
        int nb = HEADS * NTOK * JPAD;
        padb_kernel<<<(nb + 255) / 256, 256>>>(rpb, rel);
        int nm = NWIN * NTOK * JPAD;
        padm_kernel<<<(nm + 255) / 256, 256>>>(mask);
    }
    // 2) QKV GEMM
    {
        dim3 grid(C3 / BN, MTOT / BM);
        gemm_tc<CDIM><<<grid, 256>>>(x, qkv_w, qkv_b, p_qkv, MTOT, C3);
    }
    // 3) flash attention
    {
        dim3 grid(3, B_TOT * HEADS);
        attn_flash<<<grid, 256, FLASH_SMEM_BYTES>>>(p_qkv, p_ao);
    }
    // 4) proj GEMM
    {
        dim3 grid(CDIM / BN, MTOT / BM);
        gemm_tc<CDIM><<<grid, 256>>>(p_ao, proj_w, proj_b, out, MTOT, CDIM);
    }
}